// round 2
// baseline (speedup 1.0000x reference)
#include <cuda_runtime.h>

namespace {

typedef unsigned long long u64;

constexpr int HH = 256, WW = 256, CIN = 64, COUT = 64, NB = 8;
constexpr int TH = 16, TW = 16;
constexpr int XSA = 20;   // halo tile A row stride (18 cols + pad, even)
constexpr int XSB = 18;   // shifted halo tile B row stride (17 cols, even)
constexpr int SNS = 16;   // Sn tile row stride

// Packed weights: per input channel i, 10 "taps" x 64 output channels.
// taps 0..8 = conv3x3 weights (ky*3+kx), tap 9 = combined quadratic matrix M[o][i].
__device__ float g_Wt[CIN][640];
__device__ float g_bias[COUT];  // linear_b + combined quadratic bias

// ---------------- packed f32x2 helpers (Blackwell FFMA2 path) ----------------
__device__ __forceinline__ u64 fma2(u64 a, u64 b, u64 c) {
    u64 d;
    asm("fma.rn.f32x2 %0, %1, %2, %3;" : "=l"(d) : "l"(a), "l"(b), "l"(c));
    return d;
}
__device__ __forceinline__ u64 mul2(u64 a, u64 b) {
    u64 d;
    asm("mul.rn.f32x2 %0, %1, %2;" : "=l"(d) : "l"(a), "l"(b));
    return d;
}
__device__ __forceinline__ u64 add2(u64 a, u64 b) {
    u64 d;
    asm("add.rn.f32x2 %0, %1, %2;" : "=l"(d) : "l"(a), "l"(b));
    return d;
}
__device__ __forceinline__ u64 pack2(float lo, float hi) {
    u64 d;
    asm("mov.b64 %0, {%1, %2};" : "=l"(d) : "f"(lo), "f"(hi));
    return d;
}
__device__ __forceinline__ u64 lds2(const float* p) {
    return *reinterpret_cast<const u64*>(p);
}

// ---------------- weight precompute (unchanged, verified in R1) ----------------
__global__ void precompute_kernel(const float* __restrict__ lw,
                                  const float* __restrict__ lb,
                                  const float* __restrict__ w2aw,
                                  const float* __restrict__ w2ab,
                                  const float* __restrict__ w2bw,
                                  const float* __restrict__ w2bb) {
    const int i = blockIdx.x;
    const int o = threadIdx.x;

#pragma unroll
    for (int t = 0; t < 9; t++)
        g_Wt[i][t * 64 + o] = lw[(o * 64 + i) * 9 + t];

    float m = 0.f;
    for (int q = 0; q < 4; q++) {
        const float* wb = w2bw + q * 4096 + o * 64;
        const float* wa = w2aw + q * 4096 + i;
#pragma unroll 8
        for (int mm = 0; mm < 64; mm++)
            m = fmaf(wb[mm], wa[mm * 64], m);
    }
    g_Wt[i][9 * 64 + o] = m;

    if (i == 0) {
        float c = 0.f;
        for (int q = 0; q < 4; q++) {
            const float* wb = w2bw + q * 4096 + o * 64;
            const float* ab = w2ab + q * 64;
            float h = 0.f;
#pragma unroll 8
            for (int mm = 0; mm < 64; mm++) h = fmaf(wb[mm], ab[mm], h);
            c += h + w2bb[q * 64 + o];
        }
        g_bias[o] = lb[o] + c;
    }
}

// ---------------- main fused kernel ----------------
// Block: 512 threads, 16x16 pixel tile.
// thread = (ocg = tid>>5 -> 4 output channels) x (pg = tid&31 -> 8-pixel row segment).
// Math packed 2 adjacent pixels per f32x2 lane-pair: 4 oc x 4 pixel-pairs accumulators.
__global__ __launch_bounds__(512, 1)
void volterra_kernel(const float* __restrict__ x, float* __restrict__ out) {
    __shared__ __align__(16) float sxA[18 * XSA];   // halo tile (18x18), circular wrap
    __shared__ __align__(16) float sxB[18 * XSB];   // halo tile shifted left by 1 col
    __shared__ __align__(16) float ssn[16 * SNS];   // Sn tile (output pixels only)
    __shared__ __align__(16) float swd[1280];       // duplicated weight pairs (w,w) x 10 taps x 64 oc

    const int b = blockIdx.z;
    const int ty0 = blockIdx.y * TH;
    const int tx0 = blockIdx.x * TW;
    const int tid = (int)threadIdx.x;
    const int ocg = tid >> 5;        // 0..15 (warp-uniform): 4 output channels
    const int pg = tid & 31;
    const int py = pg >> 1;          // tile row 0..15
    const int pxb = (pg & 1) * 8;    // tile col base 0 or 8
    const int gy = ty0 + py;

    const bool boundary = (ty0 == 0) | (ty0 == (HH - TH)) | (tx0 == 0) | (tx0 == (WW - TW));

    u64 acc[4][4];
#pragma unroll
    for (int oo = 0; oo < 4; oo++)
#pragma unroll
        for (int kp = 0; kp < 4; kp++) acc[oo][kp] = 0ull;

    const float* xb = x + ((size_t)b << 22);

#pragma unroll 1
    for (int i = 0; i < CIN; i++) {
        __syncthreads();  // previous iteration's smem reads complete
        const float* xc = xb + ((size_t)i << 16);

        // 18x18 circular halo tile -> sxA, and left-shifted copy -> sxB
        if (tid < 324) {
            int r = tid / 18;
            int c = tid - r * 18;
            int yy = (ty0 - 1 + r) & 255;
            int xx = (tx0 - 1 + c) & 255;
            float v = xc[(yy << 8) + xx];
            sxA[r * XSA + c] = v;
            if (c > 0) sxB[r * XSB + c - 1] = v;
        }
        // duplicated weight pairs: swd[t*128 + 2o + {0,1}] = g_Wt[i][t*64 + o]
        {
            const float* wrow = g_Wt[i];
#pragma unroll
            for (int idx = tid; idx < 1280; idx += 512) {
                int t = idx >> 7;
                int o = (idx & 127) >> 1;
                swd[idx] = wrow[t * 64 + o];
            }
        }
        __syncthreads();

        // cooperative Sn tile: one pixel per thread (tid < 256)
        if (tid < 256) {
            int r = tid >> 4;
            int c = tid & 15;
            const float* sp = sxA + r * XSA + c;
            float v00 = sp[0],          v01 = sp[1],            v02 = sp[2];
            float v10 = sp[XSA],        v11 = sp[XSA + 1],      v12 = sp[XSA + 2];
            float v20 = sp[2 * XSA],    v21 = sp[2 * XSA + 1],  v22 = sp[2 * XSA + 2];
            float s = ((v00 + v01) + (v02 + v10)) +
                      ((v11 + v12) + (v20 + v21)) + v22;
            float s2 = v00 * v00;
            s2 = fmaf(v01, v01, s2); s2 = fmaf(v02, v02, s2);
            s2 = fmaf(v10, v10, s2); s2 = fmaf(v11, v11, s2);
            s2 = fmaf(v12, v12, s2); s2 = fmaf(v20, v20, s2);
            s2 = fmaf(v21, v21, s2); s2 = fmaf(v22, v22, s2);
            ssn[r * SNS + c] = fmaf(s, s, s2) * (1.0f / 90.0f);
        }
        __syncthreads();

        // main packed compute: pixel-pairs at local cols px, px+1 (px even)
#pragma unroll
        for (int kph = 0; kph < 2; kph++) {
            const int pxe0 = pxb + 4 * kph;       // pair kp = 2*kph
            const int pxe1 = pxe0 + 2;            // pair kp = 2*kph+1
            u64 c0[10], c1[10];
#pragma unroll
            for (int dyi = 0; dyi < 3; dyi++) {
                const float* rA = sxA + (py + dyi) * XSA;
                const float* rB = sxB + (py + dyi) * XSB;
                c0[dyi * 3 + 0] = lds2(rA + pxe0);      // dx=-1
                c0[dyi * 3 + 1] = lds2(rB + pxe0);      // dx= 0
                c0[dyi * 3 + 2] = lds2(rA + pxe0 + 2);  // dx=+1
                c1[dyi * 3 + 0] = lds2(rA + pxe1);
                c1[dyi * 3 + 1] = lds2(rB + pxe1);
                c1[dyi * 3 + 2] = lds2(rA + pxe1 + 2);
            }
            c0[9] = lds2(ssn + py * SNS + pxe0);
            c1[9] = lds2(ssn + py * SNS + pxe1);

            if (boundary) {
                // zero-pad masks for conv taps (Sn tap 9 stays circular)
                if (gy == 0) {
                    c0[0] = c0[1] = c0[2] = 0ull;
                    c1[0] = c1[1] = c1[2] = 0ull;
                }
                if (gy == HH - 1) {
                    c0[6] = c0[7] = c0[8] = 0ull;
                    c1[6] = c1[7] = c1[8] = 0ull;
                }
                if (kph == 0 && tx0 == 0 && pxb == 0) {
                    // pixel pair (0,1): dx=-1 low lane out of range
                    u64 m = pack2(0.f, 1.f);
                    c0[0] = mul2(c0[0], m);
                    c0[3] = mul2(c0[3], m);
                    c0[6] = mul2(c0[6], m);
                }
                if (kph == 1 && tx0 == (WW - TW) && pxb == 8) {
                    // pixel pair (254,255): dx=+1 high lane out of range
                    u64 m = pack2(1.f, 0.f);
                    c1[2] = mul2(c1[2], m);
                    c1[5] = mul2(c1[5], m);
                    c1[8] = mul2(c1[8], m);
                }
            }

#pragma unroll
            for (int oo = 0; oo < 4; oo++) {
                const float* wp = swd + ocg * 8 + oo * 2;  // broadcast LDS.64
#pragma unroll
                for (int t = 0; t < 10; t++) {
                    u64 w = lds2(wp + t * 128);
                    acc[oo][2 * kph + 0] = fma2(w, c0[t], acc[oo][2 * kph + 0]);
                    acc[oo][2 * kph + 1] = fma2(w, c1[t], acc[oo][2 * kph + 1]);
                }
            }
        }
    }

    // epilogue: + bias, 8B stores (pixel pairs contiguous, 8B aligned)
#pragma unroll
    for (int oo = 0; oo < 4; oo++) {
        const int o = ocg * 4 + oo;
        const float bo = g_bias[o];
        const u64 bp = pack2(bo, bo);
        float* dst = out + (((size_t)(b * COUT + o)) << 16) + (gy << 8) + tx0 + pxb;
#pragma unroll
        for (int kp = 0; kp < 4; kp++) {
            *reinterpret_cast<u64*>(dst + 2 * kp) = add2(acc[oo][kp], bp);
        }
    }
}

}  // namespace

extern "C" void kernel_launch(void* const* d_in, const int* in_sizes, int n_in,
                              void* d_out, int out_size) {
    (void)in_sizes; (void)n_in; (void)out_size;
    const float* x    = (const float*)d_in[0];
    const float* lw   = (const float*)d_in[1];
    const float* lb   = (const float*)d_in[2];
    const float* w2aw = (const float*)d_in[3];
    const float* w2ab = (const float*)d_in[4];
    const float* w2bw = (const float*)d_in[5];
    const float* w2bb = (const float*)d_in[6];
    float* out = (float*)d_out;

    precompute_kernel<<<CIN, 64>>>(lw, lb, w2aw, w2ab, w2bw, w2bb);
    volterra_kernel<<<dim3(WW / TW, HH / TH, NB), 512>>>(x, out);
}

// round 3
// speedup vs baseline: 1.0000x; 1.0000x over previous
#include <cuda_runtime.h>

namespace {

typedef unsigned long long u64;

constexpr int HH = 256, WW = 256, CIN = 64, COUT = 64, NB = 8;
constexpr int TH = 16, TW = 16;
constexpr int XSA = 20;   // halo tile A row stride (18 cols + pad, even)
constexpr int XSB = 18;   // shifted halo tile B row stride (17 cols, even)
constexpr int SNS = 16;   // Sn tile row stride

// Packed weights: per input channel i, 10 "taps" x 64 output channels.
// taps 0..8 = conv3x3 weights (ky*3+kx), tap 9 = combined quadratic matrix M[o][i].
__device__ float g_Wt[CIN][640];
__device__ float g_bias[COUT];  // linear_b + combined quadratic bias

// ---------------- packed f32x2 helpers (Blackwell FFMA2 path) ----------------
__device__ __forceinline__ u64 fma2(u64 a, u64 b, u64 c) {
    u64 d;
    asm("fma.rn.f32x2 %0, %1, %2, %3;" : "=l"(d) : "l"(a), "l"(b), "l"(c));
    return d;
}
__device__ __forceinline__ u64 mul2(u64 a, u64 b) {
    u64 d;
    asm("mul.rn.f32x2 %0, %1, %2;" : "=l"(d) : "l"(a), "l"(b));
    return d;
}
__device__ __forceinline__ u64 add2(u64 a, u64 b) {
    u64 d;
    asm("add.rn.f32x2 %0, %1, %2;" : "=l"(d) : "l"(a), "l"(b));
    return d;
}
__device__ __forceinline__ u64 pack2(float lo, float hi) {
    u64 d;
    asm("mov.b64 %0, {%1, %2};" : "=l"(d) : "f"(lo), "f"(hi));
    return d;
}
__device__ __forceinline__ u64 lds2(const float* p) {
    return *reinterpret_cast<const u64*>(p);
}

// ---------------- weight precompute (unchanged, verified in R1) ----------------
__global__ void precompute_kernel(const float* __restrict__ lw,
                                  const float* __restrict__ lb,
                                  const float* __restrict__ w2aw,
                                  const float* __restrict__ w2ab,
                                  const float* __restrict__ w2bw,
                                  const float* __restrict__ w2bb) {
    const int i = blockIdx.x;
    const int o = threadIdx.x;

#pragma unroll
    for (int t = 0; t < 9; t++)
        g_Wt[i][t * 64 + o] = lw[(o * 64 + i) * 9 + t];

    float m = 0.f;
    for (int q = 0; q < 4; q++) {
        const float* wb = w2bw + q * 4096 + o * 64;
        const float* wa = w2aw + q * 4096 + i;
#pragma unroll 8
        for (int mm = 0; mm < 64; mm++)
            m = fmaf(wb[mm], wa[mm * 64], m);
    }
    g_Wt[i][9 * 64 + o] = m;

    if (i == 0) {
        float c = 0.f;
        for (int q = 0; q < 4; q++) {
            const float* wb = w2bw + q * 4096 + o * 64;
            const float* ab = w2ab + q * 64;
            float h = 0.f;
#pragma unroll 8
            for (int mm = 0; mm < 64; mm++) h = fmaf(wb[mm], ab[mm], h);
            c += h + w2bb[q * 64 + o];
        }
        g_bias[o] = lb[o] + c;
    }
}

// ---------------- main fused kernel ----------------
// Block: 512 threads, 16x16 pixel tile.
// thread = (ocg = tid>>5 -> 4 output channels) x (pg = tid&31 -> 8-pixel row segment).
// Math packed 2 adjacent pixels per f32x2 lane-pair: 4 oc x 4 pixel-pairs accumulators.
__global__ __launch_bounds__(512, 1)
void volterra_kernel(const float* __restrict__ x, float* __restrict__ out) {
    __shared__ __align__(16) float sxA[18 * XSA];   // halo tile (18x18), circular wrap
    __shared__ __align__(16) float sxB[18 * XSB];   // halo tile shifted left by 1 col
    __shared__ __align__(16) float ssn[16 * SNS];   // Sn tile (output pixels only)
    __shared__ __align__(16) float swd[1280];       // duplicated weight pairs (w,w) x 10 taps x 64 oc

    const int b = blockIdx.z;
    const int ty0 = blockIdx.y * TH;
    const int tx0 = blockIdx.x * TW;
    const int tid = (int)threadIdx.x;
    const int ocg = tid >> 5;        // 0..15 (warp-uniform): 4 output channels
    const int pg = tid & 31;
    const int py = pg >> 1;          // tile row 0..15
    const int pxb = (pg & 1) * 8;    // tile col base 0 or 8
    const int gy = ty0 + py;

    const bool boundary = (ty0 == 0) | (ty0 == (HH - TH)) | (tx0 == 0) | (tx0 == (WW - TW));

    u64 acc[4][4];
#pragma unroll
    for (int oo = 0; oo < 4; oo++)
#pragma unroll
        for (int kp = 0; kp < 4; kp++) acc[oo][kp] = 0ull;

    const float* xb = x + ((size_t)b << 22);

#pragma unroll 1
    for (int i = 0; i < CIN; i++) {
        __syncthreads();  // previous iteration's smem reads complete
        const float* xc = xb + ((size_t)i << 16);

        // 18x18 circular halo tile -> sxA, and left-shifted copy -> sxB
        if (tid < 324) {
            int r = tid / 18;
            int c = tid - r * 18;
            int yy = (ty0 - 1 + r) & 255;
            int xx = (tx0 - 1 + c) & 255;
            float v = xc[(yy << 8) + xx];
            sxA[r * XSA + c] = v;
            if (c > 0) sxB[r * XSB + c - 1] = v;
        }
        // duplicated weight pairs: swd[t*128 + 2o + {0,1}] = g_Wt[i][t*64 + o]
        {
            const float* wrow = g_Wt[i];
#pragma unroll
            for (int idx = tid; idx < 1280; idx += 512) {
                int t = idx >> 7;
                int o = (idx & 127) >> 1;
                swd[idx] = wrow[t * 64 + o];
            }
        }
        __syncthreads();

        // cooperative Sn tile: one pixel per thread (tid < 256)
        if (tid < 256) {
            int r = tid >> 4;
            int c = tid & 15;
            const float* sp = sxA + r * XSA + c;
            float v00 = sp[0],          v01 = sp[1],            v02 = sp[2];
            float v10 = sp[XSA],        v11 = sp[XSA + 1],      v12 = sp[XSA + 2];
            float v20 = sp[2 * XSA],    v21 = sp[2 * XSA + 1],  v22 = sp[2 * XSA + 2];
            float s = ((v00 + v01) + (v02 + v10)) +
                      ((v11 + v12) + (v20 + v21)) + v22;
            float s2 = v00 * v00;
            s2 = fmaf(v01, v01, s2); s2 = fmaf(v02, v02, s2);
            s2 = fmaf(v10, v10, s2); s2 = fmaf(v11, v11, s2);
            s2 = fmaf(v12, v12, s2); s2 = fmaf(v20, v20, s2);
            s2 = fmaf(v21, v21, s2); s2 = fmaf(v22, v22, s2);
            ssn[r * SNS + c] = fmaf(s, s, s2) * (1.0f / 90.0f);
        }
        __syncthreads();

        // main packed compute: pixel-pairs at local cols px, px+1 (px even)
#pragma unroll
        for (int kph = 0; kph < 2; kph++) {
            const int pxe0 = pxb + 4 * kph;       // pair kp = 2*kph
            const int pxe1 = pxe0 + 2;            // pair kp = 2*kph+1
            u64 c0[10], c1[10];
#pragma unroll
            for (int dyi = 0; dyi < 3; dyi++) {
                const float* rA = sxA + (py + dyi) * XSA;
                const float* rB = sxB + (py + dyi) * XSB;
                c0[dyi * 3 + 0] = lds2(rA + pxe0);      // dx=-1
                c0[dyi * 3 + 1] = lds2(rB + pxe0);      // dx= 0
                c0[dyi * 3 + 2] = lds2(rA + pxe0 + 2);  // dx=+1
                c1[dyi * 3 + 0] = lds2(rA + pxe1);
                c1[dyi * 3 + 1] = lds2(rB + pxe1);
                c1[dyi * 3 + 2] = lds2(rA + pxe1 + 2);
            }
            c0[9] = lds2(ssn + py * SNS + pxe0);
            c1[9] = lds2(ssn + py * SNS + pxe1);

            if (boundary) {
                // zero-pad masks for conv taps (Sn tap 9 stays circular)
                if (gy == 0) {
                    c0[0] = c0[1] = c0[2] = 0ull;
                    c1[0] = c1[1] = c1[2] = 0ull;
                }
                if (gy == HH - 1) {
                    c0[6] = c0[7] = c0[8] = 0ull;
                    c1[6] = c1[7] = c1[8] = 0ull;
                }
                if (kph == 0 && tx0 == 0 && pxb == 0) {
                    // pixel pair (0,1): dx=-1 low lane out of range
                    u64 m = pack2(0.f, 1.f);
                    c0[0] = mul2(c0[0], m);
                    c0[3] = mul2(c0[3], m);
                    c0[6] = mul2(c0[6], m);
                }
                if (kph == 1 && tx0 == (WW - TW) && pxb == 8) {
                    // pixel pair (254,255): dx=+1 high lane out of range
                    u64 m = pack2(1.f, 0.f);
                    c1[2] = mul2(c1[2], m);
                    c1[5] = mul2(c1[5], m);
                    c1[8] = mul2(c1[8], m);
                }
            }

#pragma unroll
            for (int oo = 0; oo < 4; oo++) {
                const float* wp = swd + ocg * 8 + oo * 2;  // broadcast LDS.64
#pragma unroll
                for (int t = 0; t < 10; t++) {
                    u64 w = lds2(wp + t * 128);
                    acc[oo][2 * kph + 0] = fma2(w, c0[t], acc[oo][2 * kph + 0]);
                    acc[oo][2 * kph + 1] = fma2(w, c1[t], acc[oo][2 * kph + 1]);
                }
            }
        }
    }

    // epilogue: + bias, 8B stores (pixel pairs contiguous, 8B aligned)
#pragma unroll
    for (int oo = 0; oo < 4; oo++) {
        const int o = ocg * 4 + oo;
        const float bo = g_bias[o];
        const u64 bp = pack2(bo, bo);
        float* dst = out + (((size_t)(b * COUT + o)) << 16) + (gy << 8) + tx0 + pxb;
#pragma unroll
        for (int kp = 0; kp < 4; kp++) {
            *reinterpret_cast<u64*>(dst + 2 * kp) = add2(acc[oo][kp], bp);
        }
    }
}

}  // namespace

extern "C" void kernel_launch(void* const* d_in, const int* in_sizes, int n_in,
                              void* d_out, int out_size) {
    (void)in_sizes; (void)n_in; (void)out_size;
    const float* x    = (const float*)d_in[0];
    const float* lw   = (const float*)d_in[1];
    const float* lb   = (const float*)d_in[2];
    const float* w2aw = (const float*)d_in[3];
    const float* w2ab = (const float*)d_in[4];
    const float* w2bw = (const float*)d_in[5];
    const float* w2bb = (const float*)d_in[6];
    float* out = (float*)d_out;

    precompute_kernel<<<CIN, 64>>>(lw, lb, w2aw, w2ab, w2bw, w2bb);
    volterra_kernel<<<dim3(WW / TW, HH / TH, NB), 512>>>(x, out);
}

// round 5
// speedup vs baseline: 7.3269x; 7.3267x over previous
#include <cuda_runtime.h>
#include <cstdint>

namespace {

typedef unsigned int u32;

constexpr int AS_STRIDE = 41;    // words, A smem [64][41]
constexpr int BS_STRIDE = 264;   // words, B smem [40][264]
constexpr int AS_WORDS = 64 * AS_STRIDE;          // 2624
constexpr int BS_WORDS = 40 * BS_STRIDE;          // 10560
constexpr int SMEM_TOTAL = (AS_WORDS + BS_WORDS) * 4;  // 52736 B

// Global packed weights: tf32 bits, row oc (64), col k = i*10 + t (640).
// taps 0..8 = conv3x3 (ky*3+kx), tap 9 = collapsed quadratic matrix M[o][i].
__device__ u32 g_A[64 * 640];
__device__ float g_bias[64];

__device__ __forceinline__ u32 to_tf32(float f) {
    u32 r;
    asm("cvt.rna.tf32.f32 %0, %1;" : "=r"(r) : "f"(f));
    return r;
}

__device__ __forceinline__ void mma_tf32(float* d, const u32* a, u32 b0, u32 b1) {
    asm volatile(
        "mma.sync.aligned.m16n8k8.row.col.f32.tf32.tf32.f32 "
        "{%0,%1,%2,%3}, {%4,%5,%6,%7}, {%8,%9}, {%0,%1,%2,%3};"
        : "+f"(d[0]), "+f"(d[1]), "+f"(d[2]), "+f"(d[3])
        : "r"(a[0]), "r"(a[1]), "r"(a[2]), "r"(a[3]), "r"(b0), "r"(b1));
}

// grid 64 (channel i) x 64 threads (oc o)
__global__ void precompute_kernel(const float* __restrict__ lw,
                                  const float* __restrict__ lb,
                                  const float* __restrict__ w2aw,
                                  const float* __restrict__ w2ab,
                                  const float* __restrict__ w2bw,
                                  const float* __restrict__ w2bb) {
    const int i = blockIdx.x;
    const int o = threadIdx.x;

    float w[10];
#pragma unroll
    for (int t = 0; t < 9; t++) w[t] = lw[(o * 64 + i) * 9 + t];

    float m = 0.f;
    for (int q = 0; q < 4; q++) {
        const float* wb = w2bw + q * 4096 + o * 64;
        const float* wa = w2aw + q * 4096 + i;
#pragma unroll 8
        for (int mm = 0; mm < 64; mm++) m = fmaf(wb[mm], wa[mm * 64], m);
    }
    w[9] = m;  // Sn tap (Sn feature carries the /90)

#pragma unroll
    for (int t = 0; t < 10; t++)
        g_A[o * 640 + i * 10 + t] = to_tf32(w[t]);

    if (i == 0) {
        float c = 0.f;
        for (int q = 0; q < 4; q++) {
            const float* wb = w2bw + q * 4096 + o * 64;
            const float* ab = w2ab + q * 64;
            float hh = 0.f;
#pragma unroll 8
            for (int mm = 0; mm < 64; mm++) hh = fmaf(wb[mm], ab[mm], hh);
            c += hh + w2bb[q * 64 + o];
        }
        g_bias[o] = lb[o] + c;
    }
}

// 2048 CTAs (blockIdx.x = b*256 + y), 256 threads (8 warps).
// Warp w owns output tile oc[0..63] x px[w*32 .. w*32+31].
__global__ __launch_bounds__(256)
void volterra_hmma(const float* __restrict__ x, float* __restrict__ out) {
    extern __shared__ u32 smem[];
    u32* As = smem;                 // [64][41]
    u32* Bs = smem + AS_WORDS;      // [40][264]

    const int tid = (int)threadIdx.x;
    const int w = tid >> 5;
    const int lane = tid & 31;
    const int b = (int)blockIdx.x >> 8;
    const int y = (int)blockIdx.x & 255;
    const int cx = tid;             // this thread's pixel column

    const int ym1 = (y - 1) & 255, yp1 = (y + 1) & 255;
    const int xm1 = (cx - 1) & 255, xp1 = (cx + 1) & 255;
    const float* xb = x + ((size_t)b << 22);

    float acc[4][4][4];
#pragma unroll
    for (int m = 0; m < 4; m++)
#pragma unroll
        for (int n = 0; n < 4; n++)
#pragma unroll
            for (int r = 0; r < 4; r++) acc[m][n][r] = 0.f;

#pragma unroll 1
    for (int iter = 0; iter < 16; iter++) {
        __syncthreads();  // previous iteration's smem reads complete

        // ---- stage A[64][40] for channels iter*4 .. iter*4+3 ----
#pragma unroll
        for (int j = 0; j < 10; j++) {
            int idx = tid + j * 256;           // 0..2559
            int oc = idx / 40;
            int k = idx - oc * 40;
            As[oc * AS_STRIDE + k] = g_A[oc * 640 + iter * 40 + k];
        }

        // ---- build features for 4 channels, this thread's pixel ----
#pragma unroll
        for (int c = 0; c < 4; c++) {
            const float* xc = xb + ((size_t)(iter * 4 + c) << 16);
            const float* ra = xc + (ym1 << 8);
            const float* rb = xc + (y << 8);
            const float* rc = xc + (yp1 << 8);
            float v[9];
            v[0] = __ldg(ra + xm1); v[1] = __ldg(ra + cx); v[2] = __ldg(ra + xp1);
            v[3] = __ldg(rb + xm1); v[4] = __ldg(rb + cx); v[5] = __ldg(rb + xp1);
            v[6] = __ldg(rc + xm1); v[7] = __ldg(rc + cx); v[8] = __ldg(rc + xp1);

            float s = ((v[0] + v[1]) + (v[2] + v[3])) +
                      ((v[4] + v[5]) + (v[6] + v[7])) + v[8];
            float s2 = v[0] * v[0];
#pragma unroll
            for (int t = 1; t < 9; t++) s2 = fmaf(v[t], v[t], s2);
            const float Sn = fmaf(s, s, s2) * (1.0f / 90.0f);

            float f[10];
#pragma unroll
            for (int t = 0; t < 9; t++) f[t] = v[t];
            // zero-pad masks (conv taps only; Sn stays circular)
            if (y == 0)    { f[0] = 0.f; f[1] = 0.f; f[2] = 0.f; }
            if (y == 255)  { f[6] = 0.f; f[7] = 0.f; f[8] = 0.f; }
            if (cx == 0)   { f[0] = 0.f; f[3] = 0.f; f[6] = 0.f; }
            if (cx == 255) { f[2] = 0.f; f[5] = 0.f; f[8] = 0.f; }
            f[9] = Sn;

            u32* bp = Bs + (c * 10) * BS_STRIDE + cx;
#pragma unroll
            for (int t = 0; t < 10; t++) bp[t * BS_STRIDE] = to_tf32(f[t]);
        }
        __syncthreads();

        // ---- 5 k8-steps of m16n8k8 tf32 MMA ----
        const int r = lane >> 2, cc = lane & 3;
#pragma unroll
        for (int k5 = 0; k5 < 5; k5++) {
            u32 a[4][4];
#pragma unroll
            for (int m = 0; m < 4; m++) {
                const u32* ap = As + (m * 16 + r) * AS_STRIDE + k5 * 8 + cc;
                a[m][0] = ap[0];
                a[m][1] = ap[8 * AS_STRIDE];
                a[m][2] = ap[4];
                a[m][3] = ap[8 * AS_STRIDE + 4];
            }
#pragma unroll
            for (int n = 0; n < 4; n++) {
                const u32* bp = Bs + (k5 * 8 + cc) * BS_STRIDE + w * 32 + n * 8 + r;
                u32 b0 = bp[0];
                u32 b1 = bp[4 * BS_STRIDE];
#pragma unroll
                for (int m = 0; m < 4; m++) mma_tf32(acc[m][n], a[m], b0, b1);
            }
        }
    }

    // ---- epilogue: bias + float2 stores (fragment-native layout) ----
    const int r = lane >> 2, cc = lane & 3;
#pragma unroll
    for (int m = 0; m < 4; m++) {
        const int oc0 = m * 16 + r;
        const int oc1 = oc0 + 8;
        const float bo0 = g_bias[oc0];
        const float bo1 = g_bias[oc1];
        float* p0 = out + (((size_t)(b * 64 + oc0)) << 16) + (y << 8) + w * 32 + cc * 2;
        float* p1 = out + (((size_t)(b * 64 + oc1)) << 16) + (y << 8) + w * 32 + cc * 2;
#pragma unroll
        for (int n = 0; n < 4; n++) {
            float2 s0 = make_float2(acc[m][n][0] + bo0, acc[m][n][1] + bo0);
            float2 s1 = make_float2(acc[m][n][2] + bo1, acc[m][n][3] + bo1);
            *(float2*)(p0 + n * 8) = s0;
            *(float2*)(p1 + n * 8) = s1;
        }
    }
}

}  // namespace

extern "C" void kernel_launch(void* const* d_in, const int* in_sizes, int n_in,
                              void* d_out, int out_size) {
    (void)in_sizes; (void)n_in; (void)out_size;
    const float* x    = (const float*)d_in[0];
    const float* lw   = (const float*)d_in[1];
    const float* lb   = (const float*)d_in[2];
    const float* w2aw = (const float*)d_in[3];
    const float* w2ab = (const float*)d_in[4];
    const float* w2bw = (const float*)d_in[5];
    const float* w2bb = (const float*)d_in[6];
    float* out = (float*)d_out;

    static int attr_set = 0;
    if (!attr_set) {
        cudaFuncSetAttribute(volterra_hmma,
                             cudaFuncAttributeMaxDynamicSharedMemorySize, SMEM_TOTAL);
        attr_set = 1;
    }
    precompute_kernel<<<64, 64>>>(lw, lb, w2aw, w2ab, w2bw, w2bb);
    volterra_hmma<<<2048, 256, SMEM_TOTAL>>>(x, out);
}

// round 6
// speedup vs baseline: 9.0653x; 1.2373x over previous
#include <cuda_runtime.h>
#include <cstdint>

namespace {

typedef unsigned int u32;

constexpr int AST = 44;                    // A smem row stride (words)
constexpr int BST = 44;                    // B smem row stride (words)
constexpr int A_WORDS = 64 * AST;          // 2816
constexpr int B_WORDS = 256 * BST;         // 11264
constexpr int SMEM_TOTAL = (A_WORDS + B_WORDS) * 4;  // 56320 B

// Packed weights: tf32 bits, row oc (64), col k = i*10 + t (640).
// taps 0..8 = conv3x3 (ky*3+kx), tap 9 = collapsed quadratic matrix M[o][i].
__device__ u32 g_A[64 * 640];
__device__ float g_bias[64];

__device__ __forceinline__ u32 to_tf32(float f) {
    u32 r;
    asm("cvt.rna.tf32.f32 %0, %1;" : "=r"(r) : "f"(f));
    return r;
}

__device__ __forceinline__ void mma_tf32(float* d, const u32* a, u32 b0, u32 b1) {
    asm volatile(
        "mma.sync.aligned.m16n8k8.row.col.f32.tf32.tf32.f32 "
        "{%0,%1,%2,%3}, {%4,%5,%6,%7}, {%8,%9}, {%0,%1,%2,%3};"
        : "+f"(d[0]), "+f"(d[1]), "+f"(d[2]), "+f"(d[3])
        : "r"(a[0]), "r"(a[1]), "r"(a[2]), "r"(a[3]), "r"(b0), "r"(b1));
}

__device__ __forceinline__ void ldmx4(u32* r, u32 addr) {
    asm volatile("ldmatrix.sync.aligned.m8n8.x4.shared.b16 {%0,%1,%2,%3}, [%4];"
                 : "=r"(r[0]), "=r"(r[1]), "=r"(r[2]), "=r"(r[3]) : "r"(addr));
}

__device__ __forceinline__ u32 smem_u32(const void* p) {
    u32 a;
    asm("{ .reg .u64 t; cvta.to.shared.u64 t, %1; cvt.u32.u64 %0, t; }" : "=r"(a) : "l"(p));
    return a;
}

// grid 64 (channel i) x 256 threads (64 oc x 4 q-slices)
__global__ void precompute_kernel(const float* __restrict__ lw,
                                  const float* __restrict__ lb,
                                  const float* __restrict__ w2aw,
                                  const float* __restrict__ w2ab,
                                  const float* __restrict__ w2bw,
                                  const float* __restrict__ w2bb) {
    const int i = blockIdx.x;
    const int o = (int)threadIdx.x & 63;
    const int qq = (int)threadIdx.x >> 6;
    __shared__ float red[4][64];

    {
        const float* wb = w2bw + qq * 4096 + o * 64;
        const float* wa = w2aw + qq * 4096 + i;
        float m = 0.f;
#pragma unroll 8
        for (int mm = 0; mm < 64; mm++) m = fmaf(wb[mm], wa[mm * 64], m);
        red[qq][o] = m;
    }
    __syncthreads();

    if (qq == 0) {
        float w[10];
#pragma unroll
        for (int t = 0; t < 9; t++) w[t] = lw[(o * 64 + i) * 9 + t];
        w[9] = ((red[0][o] + red[1][o]) + (red[2][o] + red[3][o]));  // Sn tap
#pragma unroll
        for (int t = 0; t < 10; t++)
            g_A[o * 640 + i * 10 + t] = to_tf32(w[t]);

        if (i == 0) {
            float c = 0.f;
            for (int q = 0; q < 4; q++) {
                const float* wb = w2bw + q * 4096 + o * 64;
                const float* ab = w2ab + q * 64;
                float hh = 0.f;
#pragma unroll 8
                for (int mm = 0; mm < 64; mm++) hh = fmaf(wb[mm], ab[mm], hh);
                c += hh + w2bb[q * 64 + o];
            }
            g_bias[o] = lb[o] + c;
        }
    }
}

// 2048 CTAs (blockIdx.x = b*256 + y), 256 threads (8 warps), 2 CTAs/SM.
// Warp w owns output tile oc[0..63] x px[w*32 .. w*32+31].
// Smem: As [64 oc][44], Bs [256 px][44] (pixel-major features).
__global__ __launch_bounds__(256, 2)
void volterra_hmma(const float* __restrict__ x, float* __restrict__ out) {
    extern __shared__ u32 smem[];
    u32* As = smem;
    u32* Bs = smem + A_WORDS;
    const u32 As_b = smem_u32(smem);
    const u32 Bs_b = As_b + A_WORDS * 4;

    const int tid = (int)threadIdx.x;
    const int w = tid >> 5;
    const int lane = tid & 31;
    const int b = (int)blockIdx.x >> 8;
    const int y = (int)blockIdx.x & 255;
    const int cx = tid;  // this thread's pixel column

    const int ym1 = (y - 1) & 255, yp1 = (y + 1) & 255;
    const int xm1 = (cx - 1) & 255, xp1 = (cx + 1) & 255;
    const float* xb = x + ((size_t)b << 22);

    // ldmatrix lane-role: rows lrow (0..15), column offset lcol (0 or 4)
    const int lrow = lane & 15;
    const int lcol = (lane >> 4) * 4;

    float acc[4][4][4];
#pragma unroll
    for (int m = 0; m < 4; m++)
#pragma unroll
        for (int n = 0; n < 4; n++)
#pragma unroll
            for (int r = 0; r < 4; r++) acc[m][n][r] = 0.f;

#pragma unroll 1
    for (int iter = 0; iter < 16; iter++) {
        __syncthreads();  // previous iteration's smem reads complete

        // ---- stage A[64][40] (channels iter*4..iter*4+3), 16B vector copies ----
#pragma unroll
        for (int pass = 0; pass < 3; pass++) {
            int idx = tid + pass * 256;  // 0..639
            if (idx < 640) {
                int oc = idx / 10, j = idx - oc * 10;
                *(uint4*)(As + oc * AST + j * 4) =
                    *(const uint4*)(g_A + oc * 640 + iter * 40 + j * 4);
            }
        }

        // ---- build features pixel-major: Bs[cx][0..39], 2 channels per store pass ----
#pragma unroll
        for (int cp = 0; cp < 2; cp++) {
            u32 fv[20];
#pragma unroll
            for (int c2 = 0; c2 < 2; c2++) {
                const int ch = iter * 4 + cp * 2 + c2;
                const float* xc = xb + ((size_t)ch << 16);
                const float* ra = xc + (ym1 << 8);
                const float* rb = xc + (y << 8);
                const float* rc = xc + (yp1 << 8);
                float v[9];
                v[0] = __ldg(ra + xm1); v[1] = __ldg(ra + cx); v[2] = __ldg(ra + xp1);
                v[3] = __ldg(rb + xm1); v[4] = __ldg(rb + cx); v[5] = __ldg(rb + xp1);
                v[6] = __ldg(rc + xm1); v[7] = __ldg(rc + cx); v[8] = __ldg(rc + xp1);

                float s = ((v[0] + v[1]) + (v[2] + v[3])) +
                          ((v[4] + v[5]) + (v[6] + v[7])) + v[8];
                float s2 = v[0] * v[0];
#pragma unroll
                for (int t = 1; t < 9; t++) s2 = fmaf(v[t], v[t], s2);
                const float Sn = fmaf(s, s, s2) * (1.0f / 90.0f);

                float f[10];
#pragma unroll
                for (int t = 0; t < 9; t++) f[t] = v[t];
                // zero-pad masks (conv taps only; Sn stays circular)
                if (y == 0)    { f[0] = 0.f; f[1] = 0.f; f[2] = 0.f; }
                if (y == 255)  { f[6] = 0.f; f[7] = 0.f; f[8] = 0.f; }
                if (cx == 0)   { f[0] = 0.f; f[3] = 0.f; f[6] = 0.f; }
                if (cx == 255) { f[2] = 0.f; f[5] = 0.f; f[8] = 0.f; }
                f[9] = Sn;
#pragma unroll
                for (int t = 0; t < 10; t++) fv[c2 * 10 + t] = to_tf32(f[t]);
            }
            u32* bp = Bs + cx * BST + cp * 20;
#pragma unroll
            for (int j = 0; j < 5; j++)
                *(uint4*)(bp + j * 4) =
                    make_uint4(fv[4 * j], fv[4 * j + 1], fv[4 * j + 2], fv[4 * j + 3]);
        }
        __syncthreads();

        // ---- 5 k8-steps; fragments via ldmatrix.x4 ----
#pragma unroll
        for (int k5 = 0; k5 < 5; k5++) {
            u32 a[4][4];
#pragma unroll
            for (int m = 0; m < 4; m++)
                ldmx4(a[m], As_b + (u32)(((m * 16 + lrow) * AST + k5 * 8 + lcol) << 2));
#pragma unroll
            for (int np = 0; np < 2; np++) {
                u32 bb[4];
                ldmx4(bb, Bs_b + (u32)(((w * 32 + np * 16 + lrow) * BST + k5 * 8 + lcol) << 2));
#pragma unroll
                for (int m = 0; m < 4; m++) {
                    mma_tf32(acc[m][2 * np + 0], a[m], bb[0], bb[2]);
                    mma_tf32(acc[m][2 * np + 1], a[m], bb[1], bb[3]);
                }
            }
        }
    }

    // ---- epilogue: bias + float2 stores (fragment-native layout, verified R5) ----
    const int r = lane >> 2, cc = lane & 3;
#pragma unroll
    for (int m = 0; m < 4; m++) {
        const int oc0 = m * 16 + r;
        const int oc1 = oc0 + 8;
        const float bo0 = g_bias[oc0];
        const float bo1 = g_bias[oc1];
        float* p0 = out + (((size_t)(b * 64 + oc0)) << 16) + (y << 8) + w * 32 + cc * 2;
        float* p1 = out + (((size_t)(b * 64 + oc1)) << 16) + (y << 8) + w * 32 + cc * 2;
#pragma unroll
        for (int n = 0; n < 4; n++) {
            float2 s0 = make_float2(acc[m][n][0] + bo0, acc[m][n][1] + bo0);
            float2 s1 = make_float2(acc[m][n][2] + bo1, acc[m][n][3] + bo1);
            *(float2*)(p0 + n * 8) = s0;
            *(float2*)(p1 + n * 8) = s1;
        }
    }
}

}  // namespace

extern "C" void kernel_launch(void* const* d_in, const int* in_sizes, int n_in,
                              void* d_out, int out_size) {
    (void)in_sizes; (void)n_in; (void)out_size;
    const float* x    = (const float*)d_in[0];
    const float* lw   = (const float*)d_in[1];
    const float* lb   = (const float*)d_in[2];
    const float* w2aw = (const float*)d_in[3];
    const float* w2ab = (const float*)d_in[4];
    const float* w2bw = (const float*)d_in[5];
    const float* w2bb = (const float*)d_in[6];
    float* out = (float*)d_out;

    static int attr_set = 0;
    if (!attr_set) {
        cudaFuncSetAttribute(volterra_hmma,
                             cudaFuncAttributeMaxDynamicSharedMemorySize, SMEM_TOTAL);
        attr_set = 1;
    }
    precompute_kernel<<<64, 256>>>(lw, lb, w2aw, w2ab, w2bw, w2bb);
    volterra_hmma<<<2048, 256, SMEM_TOTAL>>>(x, out);
}

// round 7
// speedup vs baseline: 9.8423x; 1.0857x over previous
#include <cuda_runtime.h>
#include <cstdint>

namespace {

typedef unsigned int u32;

constexpr int AST = 44;                    // A smem row stride (words)
constexpr int BST = 44;                    // B smem row stride (words)
constexpr int A_WORDS = 64 * AST;          // 2816
constexpr int B_WORDS = 256 * BST;         // 11264
constexpr int SMEM_TOTAL = (A_WORDS + B_WORDS) * 4;  // 56320 B

// Packed weights: tf32 (rna) bits, row oc (64), col k = i*10 + t (640).
// taps 0..8 = conv3x3 (ky*3+kx), tap 9 = collapsed quadratic matrix M[o][i].
__device__ u32 g_A[64 * 640];
__device__ float g_bias[64];

__device__ __forceinline__ u32 to_tf32(float f) {
    u32 r;
    asm("cvt.rna.tf32.f32 %0, %1;" : "=r"(r) : "f"(f));
    return r;
}

__device__ __forceinline__ void mma_tf32(float* d, const u32* a, u32 b0, u32 b1) {
    asm volatile(
        "mma.sync.aligned.m16n8k8.row.col.f32.tf32.tf32.f32 "
        "{%0,%1,%2,%3}, {%4,%5,%6,%7}, {%8,%9}, {%0,%1,%2,%3};"
        : "+f"(d[0]), "+f"(d[1]), "+f"(d[2]), "+f"(d[3])
        : "r"(a[0]), "r"(a[1]), "r"(a[2]), "r"(a[3]), "r"(b0), "r"(b1));
}

__device__ __forceinline__ void ldmx4(u32* r, u32 addr) {
    asm volatile("ldmatrix.sync.aligned.m8n8.x4.shared.b16 {%0,%1,%2,%3}, [%4];"
                 : "=r"(r[0]), "=r"(r[1]), "=r"(r[2]), "=r"(r[3]) : "r"(addr));
}

__device__ __forceinline__ u32 smem_u32(const void* p) {
    u32 a;
    asm("{ .reg .u64 t; cvta.to.shared.u64 t, %1; cvt.u32.u64 %0, t; }" : "=r"(a) : "l"(p));
    return a;
}

__device__ __forceinline__ void cp_async16(u32 dst, const void* src) {
    asm volatile("cp.async.cg.shared.global [%0], [%1], 16;"
                 :: "r"(dst), "l"(src) : "memory");
}

// grid 64 (channel i) x 256 threads (64 oc x 4 q-slices)
__global__ void precompute_kernel(const float* __restrict__ lw,
                                  const float* __restrict__ lb,
                                  const float* __restrict__ w2aw,
                                  const float* __restrict__ w2ab,
                                  const float* __restrict__ w2bw,
                                  const float* __restrict__ w2bb) {
    const int i = blockIdx.x;
    const int o = (int)threadIdx.x & 63;
    const int qq = (int)threadIdx.x >> 6;
    __shared__ float red[4][64];

    {
        const float* wb = w2bw + qq * 4096 + o * 64;
        const float* wa = w2aw + qq * 4096 + i;
        float m = 0.f;
#pragma unroll 8
        for (int mm = 0; mm < 64; mm++) m = fmaf(wb[mm], wa[mm * 64], m);
        red[qq][o] = m;
    }
    __syncthreads();

    if (qq == 0) {
        float w[10];
#pragma unroll
        for (int t = 0; t < 9; t++) w[t] = lw[(o * 64 + i) * 9 + t];
        w[9] = ((red[0][o] + red[1][o]) + (red[2][o] + red[3][o]));  // Sn tap
#pragma unroll
        for (int t = 0; t < 10; t++)
            g_A[o * 640 + i * 10 + t] = to_tf32(w[t]);

        if (i == 0) {
            float c = 0.f;
            for (int q = 0; q < 4; q++) {
                const float* wb = w2bw + q * 4096 + o * 64;
                const float* ab = w2ab + q * 64;
                float hh = 0.f;
#pragma unroll 8
                for (int mm = 0; mm < 64; mm++) hh = fmaf(wb[mm], ab[mm], hh);
                c += hh + w2bb[q * 64 + o];
            }
            g_bias[o] = lb[o] + c;
        }
    }
}

// 2048 CTAs (blockIdx.x = b*256 + y), 256 threads (8 warps), 2 CTAs/SM.
// Warp w owns output tile oc[0..63] x px[w*32 .. w*32+31].
// Smem: As [64 oc][44], Bs [256 px][44] (pixel-major features, raw f32 bits
// fed to tf32 MMA -> HW truncation on the activation operand only).
__global__ __launch_bounds__(256, 2)
void volterra_hmma(const float* __restrict__ x, float* __restrict__ out) {
    extern __shared__ u32 smem[];
    u32* Bs = smem + A_WORDS;
    const u32 As_b = smem_u32(smem);
    const u32 Bs_b = As_b + A_WORDS * 4;

    const int tid = (int)threadIdx.x;
    const int w = tid >> 5;
    const int lane = tid & 31;
    const int b = (int)blockIdx.x >> 8;
    const int y = (int)blockIdx.x & 255;
    const int cx = tid;  // this thread's pixel column

    const int ym1 = (y - 1) & 255, yp1 = (y + 1) & 255;
    const int xm1 = (cx - 1) & 255, xp1 = (cx + 1) & 255;
    // fixed intra-channel offsets (running pointer advances by channel)
    const int oA = (ym1 << 8), oB = (y << 8), oC = (yp1 << 8);
    const float* xit = x + ((size_t)b << 22);  // advances 4 channels / iter

    // A-stage role: thread tid<160 copies one uint4 of A per iter via cp.async
    const int oc_a = tid / 10;           // valid for tid<160? no: idx mapping below
    // mapping: idx = tid (0..159) -> (oc, j): oc = idx/10... wrong: 160 idx cover
    // 64 rows x 10/4.. use: idx -> quad j of row oc where idx = oc*... 640 words =
    // 160 quads; quad q -> oc = q/10? 160/10=16 no. Correct: row has 10 quads? 40
    // words = 10 quads? 40/4 = 10 quads per row, 64 rows = 640 quads. Too many.
    // -> each of 256 threads copies 2.5.. instead: 256 threads, 640 quads: 3 passes
    // of cp.async (640 = 256+256+128).
    const u32 lds_keep = 0;  (void)lds_keep; (void)oc_a;

    // ldmatrix lane-role
    const int lrow = lane & 15;
    const int lcol = (lane >> 4) * 4;

    float acc[4][4][4];
#pragma unroll
    for (int m = 0; m < 4; m++)
#pragma unroll
        for (int n = 0; n < 4; n++)
#pragma unroll
            for (int r = 0; r < 4; r++) acc[m][n][r] = 0.f;

    // per-thread A-stage (3 passes): pass p handles quad idx = tid + p*256 (<640)
    int aq_oc[3], aq_j[3];
#pragma unroll
    for (int p = 0; p < 3; p++) {
        int idx = tid + p * 256;
        aq_oc[p] = idx / 10;             // row (may be >=64 for idx>=640 -> guarded)
        aq_j[p] = idx - aq_oc[p] * 10;   // quad within row
    }
    const u32* gA0 = g_A;                // advances by 40 per iter

#pragma unroll 1
    for (int iter = 0; iter < 16; iter++) {
        __syncthreads();  // previous iteration's smem reads complete

        // ---- stage A[64][40] via cp.async (640 quads over 256 threads) ----
#pragma unroll
        for (int p = 0; p < 3; p++) {
            int idx = tid + p * 256;
            if (idx < 640) {
                cp_async16(As_b + (u32)((aq_oc[p] * AST + aq_j[p] * 4) << 2),
                           gA0 + aq_oc[p] * 640 + aq_j[p] * 4);
            }
        }
        asm volatile("cp.async.commit_group;" ::: "memory");

        // ---- build features pixel-major: Bs[cx][0..39] (raw f32 bits) ----
#pragma unroll
        for (int cp = 0; cp < 2; cp++) {
            u32 fv[20];
#pragma unroll
            for (int c2 = 0; c2 < 2; c2++) {
                const float* xc = xit + ((size_t)(cp * 2 + c2) << 16);
                float v[9];
                v[0] = __ldg(xc + oA + xm1); v[1] = __ldg(xc + oA + cx); v[2] = __ldg(xc + oA + xp1);
                v[3] = __ldg(xc + oB + xm1); v[4] = __ldg(xc + oB + cx); v[5] = __ldg(xc + oB + xp1);
                v[6] = __ldg(xc + oC + xm1); v[7] = __ldg(xc + oC + cx); v[8] = __ldg(xc + oC + xp1);

                float s = ((v[0] + v[1]) + (v[2] + v[3])) +
                          ((v[4] + v[5]) + (v[6] + v[7])) + v[8];
                float s2 = v[0] * v[0];
#pragma unroll
                for (int t = 1; t < 9; t++) s2 = fmaf(v[t], v[t], s2);
                const float Sn = fmaf(s, s, s2) * (1.0f / 90.0f);

                float f[10];
#pragma unroll
                for (int t = 0; t < 9; t++) f[t] = v[t];
                // zero-pad masks (conv taps only; Sn stays circular)
                if (y == 0)    { f[0] = 0.f; f[1] = 0.f; f[2] = 0.f; }
                if (y == 255)  { f[6] = 0.f; f[7] = 0.f; f[8] = 0.f; }
                if (cx == 0)   { f[0] = 0.f; f[3] = 0.f; f[6] = 0.f; }
                if (cx == 255) { f[2] = 0.f; f[5] = 0.f; f[8] = 0.f; }
                f[9] = Sn;
#pragma unroll
                for (int t = 0; t < 10; t++) fv[c2 * 10 + t] = __float_as_uint(f[t]);
            }
            u32* bp = Bs + cx * BST + cp * 20;
#pragma unroll
            for (int j = 0; j < 5; j++)
                *(uint4*)(bp + j * 4) =
                    make_uint4(fv[4 * j], fv[4 * j + 1], fv[4 * j + 2], fv[4 * j + 3]);
        }
        xit += (size_t)4 << 16;
        gA0 += 40;

        asm volatile("cp.async.wait_group 0;" ::: "memory");
        __syncthreads();

        // ---- 5 k8-steps; fragments via ldmatrix.x4 ----
#pragma unroll
        for (int k5 = 0; k5 < 5; k5++) {
            u32 a[4][4];
#pragma unroll
            for (int m = 0; m < 4; m++)
                ldmx4(a[m], As_b + (u32)(((m * 16 + lrow) * AST + k5 * 8 + lcol) << 2));
#pragma unroll
            for (int np = 0; np < 2; np++) {
                u32 bb[4];
                ldmx4(bb, Bs_b + (u32)(((w * 32 + np * 16 + lrow) * BST + k5 * 8 + lcol) << 2));
#pragma unroll
                for (int m = 0; m < 4; m++) {
                    mma_tf32(acc[m][2 * np + 0], a[m], bb[0], bb[2]);
                    mma_tf32(acc[m][2 * np + 1], a[m], bb[1], bb[3]);
                }
            }
        }
    }

    // ---- epilogue: bias + float2 stores (fragment-native layout, verified) ----
    const int r = lane >> 2, cc = lane & 3;
#pragma unroll
    for (int m = 0; m < 4; m++) {
        const int oc0 = m * 16 + r;
        const int oc1 = oc0 + 8;
        const float bo0 = g_bias[oc0];
        const float bo1 = g_bias[oc1];
        float* p0 = out + (((size_t)(b * 64 + oc0)) << 16) + (y << 8) + w * 32 + cc * 2;
        float* p1 = out + (((size_t)(b * 64 + oc1)) << 16) + (y << 8) + w * 32 + cc * 2;
#pragma unroll
        for (int n = 0; n < 4; n++) {
            float2 s0 = make_float2(acc[m][n][0] + bo0, acc[m][n][1] + bo0);
            float2 s1 = make_float2(acc[m][n][2] + bo1, acc[m][n][3] + bo1);
            *(float2*)(p0 + n * 8) = s0;
            *(float2*)(p1 + n * 8) = s1;
        }
    }
}

}  // namespace

extern "C" void kernel_launch(void* const* d_in, const int* in_sizes, int n_in,
                              void* d_out, int out_size) {
    (void)in_sizes; (void)n_in; (void)out_size;
    const float* x    = (const float*)d_in[0];
    const float* lw   = (const float*)d_in[1];
    const float* lb   = (const float*)d_in[2];
    const float* w2aw = (const float*)d_in[3];
    const float* w2ab = (const float*)d_in[4];
    const float* w2bw = (const float*)d_in[5];
    const float* w2bb = (const float*)d_in[6];
    float* out = (float*)d_out;

    static int attr_set = 0;
    if (!attr_set) {
        cudaFuncSetAttribute(volterra_hmma,
                             cudaFuncAttributeMaxDynamicSharedMemorySize, SMEM_TOTAL);
        attr_set = 1;
    }
    precompute_kernel<<<64, 256>>>(lw, lb, w2aw, w2ab, w2bw, w2bb);
    volterra_hmma<<<2048, 256, SMEM_TOTAL>>>(x, out);
}